// round 10
// baseline (speedup 1.0000x reference)
#include <cuda_runtime.h>

#define NN 131072
#define EE 2097152
#define GB 8
#define CWD 64
#define NB 592
#define NT 256
#define GT (NB * NT)
#define NWARPS (GT / 32)
#define NGRP 37
#define GRPSZ 16

// ---------------- static device scratch ----------------
__device__ int d_cnt[NN];
__device__ int d_rowptr[NN + 1];
__device__ int d_cursor[NN];
__device__ int d_csr_src[EE];
__device__ int d_blocksums[128];
__device__ float d_hA[NN * CWD];
__device__ float d_hB[NN * CWD];
__device__ float d_xw[NN * CWD];
__device__ float d_score[NN];
__device__ float d_dis[NN];
__device__ int d_c2oA[NN];
__device__ int d_c2oB[NN];
__device__ int d_o2c[NN];
__device__ int d_oldidx[NN];
__device__ unsigned d_thresh[GB];
__device__ int d_quota[GB];
__device__ int d_ctr[GB];
__device__ int d_eq[GB];
__device__ unsigned d_romax[4 * GB * CWD];
__device__ float d_rosum[4 * GB * CWD];
__device__ float d_WT[4][CWD * CWD];

// tree grid-barrier state
__device__ int g_cnt[NGRP];
__device__ int g_root;
__device__ volatile int g_gen;

__device__ __forceinline__ unsigned fkey(float f) {
    unsigned b = __float_as_uint(f);
    return (b & 0x80000000u) ? ~b : (b | 0x80000000u);
}
__device__ __forceinline__ float unfkey(unsigned u) {
    unsigned b = (u & 0x80000000u) ? (u & 0x7fffffffu) : ~u;
    return __uint_as_float(b);
}

__device__ __forceinline__ void gridbar() {
    __syncthreads();
    if (threadIdx.x == 0) {
        int gen = g_gen;
        __threadfence();
        int grp = blockIdx.x >> 4;   // 592 = 37 * 16 exactly
        if (atomicAdd(&g_cnt[grp], 1) == GRPSZ - 1) {
            g_cnt[grp] = 0;
            __threadfence();
            if (atomicAdd(&g_root, 1) == NGRP - 1) {
                g_root = 0;
                __threadfence();
                g_gen = gen + 1;
            }
        }
        while (g_gen == gen) __nanosleep(128);
        __threadfence();
    }
    __syncthreads();
}

__device__ __forceinline__ int wscan_incl(int v, int lane) {
    int incl = v;
    #pragma unroll
    for (int off = 1; off < 32; off <<= 1) {
        int n = __shfl_up_sync(0xffffffffu, incl, off);
        if (lane >= off) incl += n;
    }
    return incl;
}

// ---------------- the megakernel ----------------
__global__ void __launch_bounds__(NT, 4) mega_kernel(
    const float* __restrict__ x, const int* __restrict__ ei,
    const float* __restrict__ Wl1, const float* __restrict__ bl1, const float* __restrict__ Wr1,
    const float* __restrict__ Wl2, const float* __restrict__ bl2, const float* __restrict__ Wr2,
    const float* __restrict__ W4, const float* __restrict__ b4,
    const float* __restrict__ W5, const float* __restrict__ b5,
    const float* __restrict__ wp1, const float* __restrict__ wp2,
    const float* __restrict__ wp4, const float* __restrict__ wp5,
    const float* __restrict__ Wa, const float* __restrict__ ba,
    const float* __restrict__ Wb, const float* __restrict__ bb,
    const float* __restrict__ Wc, const float* __restrict__ bc,
    float* __restrict__ out)
{
    __shared__ float s_f[4608];
    __shared__ unsigned s_pref;
    __shared__ int s_rem;
    int* s_i = (int*)s_f;
    unsigned* s_u = (unsigned*)s_f;

    const int t = threadIdx.x;
    const int lane = t & 31;
    const int w = t >> 5;
    const int gtid = blockIdx.x * NT + t;
    const int gwarp = gtid >> 5;
    const int* src = ei;
    const int* dst = ei + EE;

    // ---- ph0: init + weight transpose ----
    for (int i = gtid; i < NN; i += GT) { d_cnt[i] = 0; d_c2oA[i] = i; }
    for (int i = gtid; i < 4 * GB * CWD; i += GT) { d_romax[i] = 0u; d_rosum[i] = 0.f; }
    for (int i = gtid; i < 4 * 4096; i += GT) {
        int slot = i >> 12, j = i & 4095;
        const float* W = slot == 0 ? Wl2 : slot == 1 ? Wr2 : slot == 2 ? W4 : W5;
        int r = j >> 6, c = j & 63;
        d_WT[slot][c * 64 + r] = W[j];
    }
    gridbar();

    // ---- ph1: histogram ----
    for (int e = gtid; e < EE; e += GT) atomicAdd(&d_cnt[dst[e]], 1);
    gridbar();

    // ---- ph2: per-chunk scan (blocks 0..127) ----
    if (blockIdx.x < 128) {
        int base = blockIdx.x * 1024;
        int i0 = base + t * 4;
        int v0 = d_cnt[i0], v1 = d_cnt[i0 + 1], v2 = d_cnt[i0 + 2], v3 = d_cnt[i0 + 3];
        int s = v0 + v1 + v2 + v3;
        int incl = wscan_incl(s, lane);
        if (lane == 31) s_i[w] = incl;
        __syncthreads();
        if (t == 0) {
            int acc = 0;
            #pragma unroll
            for (int ww = 0; ww < 8; ww++) { int tmp = s_i[ww]; s_i[ww] = acc; acc += tmp; }
        }
        __syncthreads();
        int ex = s_i[w] + incl - s;
        d_rowptr[i0] = ex;
        d_rowptr[i0 + 1] = ex + v0;
        d_rowptr[i0 + 2] = ex + v0 + v1;
        d_rowptr[i0 + 3] = ex + v0 + v1 + v2;
        if (t == NT - 1) d_blocksums[blockIdx.x] = ex + s;
    }
    gridbar();

    // ---- ph3: scan of 128 blocksums ----
    if (blockIdx.x == 0 && t < 32) {
        int i0 = lane * 4;
        int v0 = d_blocksums[i0], v1 = d_blocksums[i0 + 1], v2 = d_blocksums[i0 + 2], v3 = d_blocksums[i0 + 3];
        int s = v0 + v1 + v2 + v3;
        int incl = wscan_incl(s, lane);
        int ex = incl - s;
        d_blocksums[i0] = ex;
        d_blocksums[i0 + 1] = ex + v0;
        d_blocksums[i0 + 2] = ex + v0 + v1;
        d_blocksums[i0 + 3] = ex + v0 + v1 + v2;
    }
    gridbar();

    // ---- ph4: add chunk offsets ----
    for (int i = gtid; i < NN; i += GT) {
        int r = d_rowptr[i] + d_blocksums[i >> 10];
        d_rowptr[i] = r;
        d_cursor[i] = r;
    }
    if (gtid == 0) d_rowptr[NN] = EE;
    gridbar();

    // ---- ph5: scatter edges ----
    for (int e = gtid; e < EE; e += GT) {
        int p = atomicAdd(&d_cursor[dst[e]], 1);
        d_csr_src[p] = src[e];
    }
    gridbar();

    // ---- ph6: conv1 SAGE (2->64) ----
    {
        const float2* x2 = (const float2*)x;
        for (int n = gwarp; n < NN; n += NWARPS) {
            int row = d_rowptr[n], end = d_rowptr[n + 1];
            float a0 = 0.f, a1 = 0.f;
            for (int e = row + lane; e < end; e += 32) {
                float2 v = x2[d_csr_src[e]];
                a0 += v.x; a1 += v.y;
            }
            for (int o = 16; o; o >>= 1) {
                a0 += __shfl_xor_sync(0xffffffffu, a0, o);
                a1 += __shfl_xor_sync(0xffffffffu, a1, o);
            }
            float deg = (float)(end - row);
            float inv = deg > 0.f ? 1.f / deg : 0.f;
            float m0 = a0 * inv, m1 = a1 * inv;
            float2 xv = x2[n];
            int d0 = lane, d1 = lane + 32;
            float o0 = Wl1[d0 * 2] * m0 + Wl1[d0 * 2 + 1] * m1 + bl1[d0] + Wr1[d0 * 2] * xv.x + Wr1[d0 * 2 + 1] * xv.y;
            float o1 = Wl1[d1 * 2] * m0 + Wl1[d1 * 2 + 1] * m1 + bl1[d1] + Wr1[d1 * 2] * xv.x + Wr1[d1 * 2 + 1] * xv.y;
            o0 = fmaxf(o0, 0.f); o1 = fmaxf(o1, 0.f);
            d_hA[n * 64 + d0] = o0;
            d_hA[n * 64 + d1] = o1;
            float w0 = wp1[d0], w1 = wp1[d1];
            float sd = o0 * w0 + o1 * w1, nw = w0 * w0 + w1 * w1;
            for (int o = 16; o; o >>= 1) {
                sd += __shfl_xor_sync(0xffffffffu, sd, o);
                nw += __shfl_xor_sync(0xffffffffu, nw, o);
            }
            if (lane == 0) d_score[n] = tanhf(sd * rsqrtf(nw));
        }
    }
    gridbar();

    // ================= 4 stages of pool / conv =================
    #pragma unroll 1
    for (int stage = 0; stage < 4; stage++) {
        int m = 16384 >> stage;
        int k = m >> 1;
        int shift = 14 - stage;
        int flip = stage & 1;

        // ---- select (blocks 0..7) ----
        if (blockIdx.x < GB) {
            int b = blockIdx.x;
            int base = b * m;
            if (t == 0) { s_pref = 0u; s_rem = k; }
            __syncthreads();
            for (int p = 3; p >= 0; p--) {
                if (t < 256) s_u[t] = 0;
                __syncthreads();
                unsigned pref = s_pref;
                int hs = (p + 1) * 8;
                for (int i = t; i < m; i += NT) {
                    unsigned u = fkey(d_score[base + i]);
                    bool cand = (p == 3) || ((u >> hs) == (pref >> hs));
                    if (cand) atomicAdd(&s_u[(u >> (p * 8)) & 255], 1u);
                }
                __syncthreads();
                if (t == 0) {
                    int rem = s_rem;
                    unsigned c = 0;
                    for (int bb = 255; bb >= 0; bb--) {
                        if (c + s_u[bb] >= (unsigned)rem) {
                            s_pref = pref | ((unsigned)bb << (p * 8));
                            s_rem = rem - (int)c;
                            break;
                        }
                        c += s_u[bb];
                    }
                }
                __syncthreads();
            }
            if (t == 0) {
                d_thresh[b] = s_pref;
                d_quota[b] = s_rem;
                d_ctr[b] = 0;
                d_eq[b] = 0;
            }
        }
        gridbar();

        // ---- compact (warp-aggregated counter atomics) ----
        {
            int lim = GB * m;
            int iters = (lim + GT - 1) / GT;
            const int* oldm = flip ? d_c2oB : d_c2oA;
            int* newm = flip ? d_c2oA : d_c2oB;
            for (int it = 0; it < iters; it++) {
                int c = gtid + it * GT;
                bool valid = c < lim;
                int cc = valid ? c : (lim - 1);
                int b = cc >> shift;
                unsigned u = fkey(d_score[cc]);
                unsigned th = d_thresh[b];
                int orig = oldm[cc];
                bool keep = valid && (u > th);
                if (valid && !keep && u == th)
                    keep = (atomicAdd(&d_eq[b], 1) < d_quota[b]);
                __syncwarp();
                unsigned same = __match_any_sync(0xffffffffu, b);
                unsigned keepers = __ballot_sync(0xffffffffu, keep) & same;
                int leader = __ffs(same) - 1;
                int cnt = __popc(keepers);
                int base_slot = 0;
                if (lane == leader && cnt > 0) base_slot = atomicAdd(&d_ctr[b], cnt);
                base_slot = __shfl_sync(0xffffffffu, base_slot, leader);
                if (keep) {
                    int slot = base_slot + __popc(keepers & ((1u << lane) - 1));
                    int nc = b * k + slot;
                    newm[nc] = orig;
                    d_o2c[orig] = nc;
                    d_oldidx[nc] = c;
                } else if (valid) {
                    d_o2c[orig] = -1;
                }
            }
        }
        gridbar();

        // ---- pool copy + fused readout partials ----
        {
            int ntiles = GB * k / 16;
            for (int tile = blockIdx.x; tile < ntiles; tile += NB) {
                #pragma unroll
                for (int q = 0; q < 2; q++) {
                    int r = w * 2 + q;
                    int gw2 = tile * 16 + r;
                    int oldc = d_oldidx[gw2];
                    float v = d_score[oldc];
                    float2 h = *(const float2*)&d_hA[oldc * 64 + 2 * lane];
                    float v0 = h.x * v, v1 = h.y * v;
                    *(float2*)&d_hB[gw2 * 64 + 2 * lane] = make_float2(v0, v1);
                    s_f[r * 64 + 2 * lane] = v0;
                    s_f[r * 64 + 2 * lane + 1] = v1;
                }
                __syncthreads();
                if (t < 64) {
                    float mx = s_f[t], sm = 0.f;
                    #pragma unroll
                    for (int rr = 0; rr < 16; rr++) {
                        float f = s_f[rr * 64 + t];
                        mx = fmaxf(mx, f);
                        sm += f;
                    }
                    int b = (tile * 16) / k;
                    int off = stage * GB * 64 + b * 64 + t;
                    atomicMax(&d_romax[off], fkey(mx));
                    atomicAdd(&d_rosum[off], sm);
                }
                __syncthreads();
            }
        }
        gridbar();

        if (stage == 3) break;

        int M = GB * k;
        const int* c2o = flip ? d_c2oA : d_c2oB;

        if (stage == 0) {
            // ======== SAGE2: agg then transform ========
            for (int n = gwarp; n < M; n += NWARPS) {
                int o = c2o[n];
                int row = d_rowptr[o], end = d_rowptr[o + 1];
                float a0 = 0.f, a1 = 0.f;
                int cnt = 0;
                for (int base = row; base < end; base += 32) {
                    int e = base + lane;
                    int sc = -1;
                    if (e < end) sc = d_o2c[d_csr_src[e]];
                    unsigned liveb = __ballot_sync(0xffffffffu, sc >= 0);
                    cnt += __popc(liveb);
                    while (liveb) {
                        int j = __ffs(liveb) - 1;
                        liveb &= liveb - 1;
                        int scj = __shfl_sync(0xffffffffu, sc, j);
                        float2 v = *(const float2*)&d_hB[scj * 64 + 2 * lane];
                        a0 += v.x; a1 += v.y;
                    }
                }
                float invc = cnt ? 1.f / (float)cnt : 0.f;
                *(float2*)&d_xw[n * 64 + 2 * lane] = make_float2(a0 * invc, a1 * invc);
            }
            gridbar();
            {
                const float* WlT = d_WT[0];
                const float* WrT = d_WT[1];
                float b0 = bl2[lane], b1 = bl2[lane + 32];
                float w0 = wp2[lane], w1 = wp2[lane + 32];
                float nw = w0 * w0 + w1 * w1;
                for (int o = 16; o; o >>= 1) nw += __shfl_xor_sync(0xffffffffu, nw, o);
                float rn = rsqrtf(nw);
                for (int pair = gwarp; pair < M / 2; pair += NWARPS) {
                    int n0 = pair * 2;
                    float mA[2], mB[2], hA[2], hB[2], o0[2], o1[2];
                    #pragma unroll
                    for (int q = 0; q < 2; q++) {
                        int n = n0 + q;
                        mA[q] = d_xw[n * 64 + lane];
                        mB[q] = d_xw[n * 64 + lane + 32];
                        hA[q] = d_hB[n * 64 + lane];
                        hB[q] = d_hB[n * 64 + lane + 32];
                        o0[q] = 0.f; o1[q] = 0.f;
                    }
                    #pragma unroll 4
                    for (int j = 0; j < 32; j++) {
                        float wl0 = __ldg(&WlT[j * 64 + lane]), wl1 = __ldg(&WlT[j * 64 + lane + 32]);
                        float wr0 = __ldg(&WrT[j * 64 + lane]), wr1 = __ldg(&WrT[j * 64 + lane + 32]);
                        #pragma unroll
                        for (int q = 0; q < 2; q++) {
                            float mj = __shfl_sync(0xffffffffu, mA[q], j);
                            float hj = __shfl_sync(0xffffffffu, hA[q], j);
                            o0[q] += wl0 * mj + wr0 * hj;
                            o1[q] += wl1 * mj + wr1 * hj;
                        }
                    }
                    #pragma unroll 4
                    for (int j = 32; j < 64; j++) {
                        float wl0 = __ldg(&WlT[j * 64 + lane]), wl1 = __ldg(&WlT[j * 64 + lane + 32]);
                        float wr0 = __ldg(&WrT[j * 64 + lane]), wr1 = __ldg(&WrT[j * 64 + lane + 32]);
                        #pragma unroll
                        for (int q = 0; q < 2; q++) {
                            float mj = __shfl_sync(0xffffffffu, mB[q], j - 32);
                            float hj = __shfl_sync(0xffffffffu, hB[q], j - 32);
                            o0[q] += wl0 * mj + wr0 * hj;
                            o1[q] += wl1 * mj + wr1 * hj;
                        }
                    }
                    #pragma unroll
                    for (int q = 0; q < 2; q++) {
                        int n = n0 + q;
                        float r0 = fmaxf(o0[q] + b0, 0.f);
                        float r1 = fmaxf(o1[q] + b1, 0.f);
                        d_hA[n * 64 + lane] = r0;
                        d_hA[n * 64 + lane + 32] = r1;
                        float sd = r0 * w0 + r1 * w1;
                        for (int o = 16; o; o >>= 1) sd += __shfl_xor_sync(0xffffffffu, sd, o);
                        if (lane == 0) d_score[n] = tanhf(sd * rn);
                    }
                }
            }
            gridbar();
        } else {
            // ======== GCN: xw transform + degree, then aggregate ========
            int slot = stage + 1;
            const float* bias = (stage == 1) ? b4 : b5;
            const float* wp = (stage == 1) ? wp4 : wp5;
            {
                const float* WT = d_WT[slot];
                for (int pair = gwarp; pair < M / 2; pair += NWARPS) {
                    int n0 = pair * 2;
                    float hA[2], hB[2], o0[2], o1[2];
                    #pragma unroll
                    for (int q = 0; q < 2; q++) {
                        int n = n0 + q;
                        hA[q] = d_hB[n * 64 + lane];
                        hB[q] = d_hB[n * 64 + lane + 32];
                        o0[q] = 0.f; o1[q] = 0.f;
                    }
                    #pragma unroll 4
                    for (int j = 0; j < 32; j++) {
                        float w0 = __ldg(&WT[j * 64 + lane]), w1 = __ldg(&WT[j * 64 + lane + 32]);
                        #pragma unroll
                        for (int q = 0; q < 2; q++) {
                            float hj = __shfl_sync(0xffffffffu, hA[q], j);
                            o0[q] += w0 * hj;
                            o1[q] += w1 * hj;
                        }
                    }
                    #pragma unroll 4
                    for (int j = 32; j < 64; j++) {
                        float w0 = __ldg(&WT[j * 64 + lane]), w1 = __ldg(&WT[j * 64 + lane + 32]);
                        #pragma unroll
                        for (int q = 0; q < 2; q++) {
                            float hj = __shfl_sync(0xffffffffu, hB[q], j - 32);
                            o0[q] += w0 * hj;
                            o1[q] += w1 * hj;
                        }
                    }
                    #pragma unroll
                    for (int q = 0; q < 2; q++) {
                        int n = n0 + q;
                        d_xw[n * 64 + lane] = o0[q];
                        d_xw[n * 64 + lane + 32] = o1[q];
                        int o = c2o[n];
                        int row = d_rowptr[o], end = d_rowptr[o + 1];
                        int cnt = 0;
                        for (int base = row; base < end; base += 32) {
                            int e = base + lane;
                            bool live = false;
                            if (e < end) live = (d_o2c[d_csr_src[e]] >= 0);
                            cnt += __popc(__ballot_sync(0xffffffffu, live));
                        }
                        if (lane == 0) d_dis[n] = rsqrtf(1.f + (float)cnt);
                    }
                }
            }
            gridbar();
            for (int n = gwarp; n < M; n += NWARPS) {
                int o = c2o[n];
                float dd = d_dis[n];
                int row = d_rowptr[o], end = d_rowptr[o + 1];
                float a0 = 0.f, a1 = 0.f;
                for (int base = row; base < end; base += 32) {
                    int e = base + lane;
                    int sc = -1;
                    float ds = 0.f;
                    if (e < end) {
                        sc = d_o2c[d_csr_src[e]];
                        if (sc >= 0) ds = d_dis[sc];
                    }
                    unsigned liveb = __ballot_sync(0xffffffffu, sc >= 0);
                    while (liveb) {
                        int j = __ffs(liveb) - 1;
                        liveb &= liveb - 1;
                        int scj = __shfl_sync(0xffffffffu, sc, j);
                        float dsj = __shfl_sync(0xffffffffu, ds, j);
                        float2 v = *(const float2*)&d_xw[scj * 64 + 2 * lane];
                        a0 += v.x * dsj;
                        a1 += v.y * dsj;
                    }
                }
                a0 *= dd; a1 *= dd;
                float2 self = *(const float2*)&d_xw[n * 64 + 2 * lane];
                float o0 = a0 + self.x * dd * dd + bias[2 * lane];
                float o1 = a1 + self.y * dd * dd + bias[2 * lane + 1];
                o0 = fmaxf(o0, 0.f); o1 = fmaxf(o1, 0.f);
                *(float2*)&d_hA[n * 64 + 2 * lane] = make_float2(o0, o1);
                float w0 = wp[2 * lane], w1 = wp[2 * lane + 1];
                float sd = o0 * w0 + o1 * w1, nw = w0 * w0 + w1 * w1;
                for (int s = 16; s; s >>= 1) {
                    sd += __shfl_xor_sync(0xffffffffu, sd, s);
                    nw += __shfl_xor_sync(0xffffffffu, nw, s);
                }
                if (lane == 0) d_score[n] = tanhf(sd * rsqrtf(nw));
            }
            gridbar();
        }
    }

    // ---- final MLP + softmax (block 0) ----
    if (blockIdx.x == 0) {
        float* zs = s_f;
        float* za = s_f + 1024;
        float* zb = s_f + 2048;
        float* zc = s_f + 2560;
        const float invk[4] = {1.f / 8192.f, 1.f / 4096.f, 1.f / 2048.f, 1.f / 1024.f};
        for (int q = t; q < 1024; q += NT) {
            int b = q >> 7, d = q & 127;
            float acc = 0.f;
            if (d < 64) {
                #pragma unroll
                for (int st = 0; st < 4; st++)
                    acc += unfkey(d_romax[st * GB * 64 + b * 64 + d]);
            } else {
                #pragma unroll
                for (int st = 0; st < 4; st++)
                    acc += d_rosum[st * GB * 64 + b * 64 + (d - 64)] * invk[st];
            }
            zs[q] = acc;
        }
        __syncthreads();
        for (int q = t; q < 1024; q += NT) {
            int b = q >> 7, o = q & 127;
            float a = ba[o];
            const float* wv = Wa + o * 128;
            const float* z = zs + b * 128;
            for (int j = 0; j < 128; j++) a += wv[j] * z[j];
            za[q] = fmaxf(a, 0.f);
        }
        __syncthreads();
        for (int q = t; q < 512; q += NT) {
            int b = q >> 6, o = q & 63;
            float a = bb[o];
            for (int j = 0; j < 128; j++) a += Wb[o * 128 + j] * za[b * 128 + j];
            zb[q] = fmaxf(a, 0.f);
        }
        __syncthreads();
        for (int q = t; q < 2048; q += NT) {
            int b = q >> 8, o = q & 255;
            float a = bc[o];
            for (int j = 0; j < 64; j++) a += Wc[o * 64 + j] * zb[b * 64 + j];
            zc[q] = a;
        }
        __syncthreads();
        {
            float mx = -3.4e38f;
            for (int i = lane; i < 256; i += 32) mx = fmaxf(mx, zc[w * 256 + i]);
            for (int o = 16; o; o >>= 1) mx = fmaxf(mx, __shfl_xor_sync(0xffffffffu, mx, o));
            float s = 0.f;
            for (int i = lane; i < 256; i += 32) {
                float e = expf(zc[w * 256 + i] - mx);
                zc[w * 256 + i] = e;
                s += e;
            }
            for (int o = 16; o; o >>= 1) s += __shfl_xor_sync(0xffffffffu, s, o);
            float inv = 1.f / s;
            for (int i = lane; i < 256; i += 32) out[w * 256 + i] = zc[w * 256 + i] * inv;
        }
    }
}

// ---------------- launch ----------------
extern "C" void kernel_launch(void* const* d_in, const int* in_sizes, int n_in,
                              void* d_out, int out_size) {
    mega_kernel<<<NB, NT>>>(
        (const float*)d_in[0], (const int*)d_in[1],
        (const float*)d_in[2], (const float*)d_in[3], (const float*)d_in[4],
        (const float*)d_in[5], (const float*)d_in[6], (const float*)d_in[7],
        (const float*)d_in[8], (const float*)d_in[9],
        (const float*)d_in[10], (const float*)d_in[11],
        (const float*)d_in[12], (const float*)d_in[13],
        (const float*)d_in[14], (const float*)d_in[15],
        (const float*)d_in[16], (const float*)d_in[17],
        (const float*)d_in[18], (const float*)d_in[19],
        (const float*)d_in[20], (const float*)d_in[21],
        (float*)d_out);
}

// round 11
// speedup vs baseline: 1.6893x; 1.6893x over previous
#include <cuda_runtime.h>

#define NN 131072
#define EE 2097152
#define GB 8
#define CWD 64

// ---------------- static device scratch ----------------
__device__ int d_cnt[NN];
__device__ int d_rowptr[NN + 1];
__device__ int d_cursor[NN];
__device__ int d_csr_src[EE];
__device__ int d_blocksums[128];
__device__ float d_hA[NN * CWD];
__device__ float d_hB[NN * CWD];
__device__ float d_xw[NN * CWD];
__device__ float d_score[NN];
__device__ float d_dis[NN];
__device__ int d_c2oA[NN];
__device__ int d_c2oB[NN];
__device__ int d_o2c[NN];
__device__ int d_oldidx[NN];
__device__ unsigned d_romax[4 * GB * CWD];
__device__ float d_rosum[4 * GB * CWD];
__device__ float d_WT[4][CWD * CWD];  // transposed Wl2, Wr2, W4, W5

__device__ __forceinline__ unsigned fkey(float f) {
    unsigned b = __float_as_uint(f);
    return (b & 0x80000000u) ? ~b : (b | 0x80000000u);
}
__device__ __forceinline__ float unfkey(unsigned u) {
    unsigned b = (u & 0x80000000u) ? (u & 0x7fffffffu) : ~u;
    return __uint_as_float(b);
}

// ---------------- CSR build + weight transpose ----------------
__global__ void init_kernel(const float* __restrict__ Wl2, const float* __restrict__ Wr2,
                            const float* __restrict__ W4, const float* __restrict__ W5) {
    int i = blockIdx.x * blockDim.x + threadIdx.x;
    if (i < NN) { d_cnt[i] = 0; d_c2oA[i] = i; }
    if (i < 4 * GB * CWD) { d_romax[i] = 0u; d_rosum[i] = 0.f; }
    if (i < 4 * 4096) {
        int slot = i >> 12;
        int j = i & 4095;
        const float* W = slot == 0 ? Wl2 : slot == 1 ? Wr2 : slot == 2 ? W4 : W5;
        int r = j >> 6, c = j & 63;
        d_WT[slot][c * 64 + r] = W[j];
    }
}

__global__ void hist_kernel(const int* __restrict__ dst) {
    int e = blockIdx.x * blockDim.x + threadIdx.x;
    if (e < EE) atomicAdd(&d_cnt[dst[e]], 1);
}

__global__ void __launch_bounds__(1024, 1) scan1_kernel() {
    __shared__ int s[1024];
    int t = threadIdx.x, i = blockIdx.x * 1024 + t;
    int v = d_cnt[i];
    s[t] = v; __syncthreads();
    for (int off = 1; off < 1024; off <<= 1) {
        int tmp = (t >= off) ? s[t - off] : 0;
        __syncthreads();
        s[t] += tmp;
        __syncthreads();
    }
    d_rowptr[i] = s[t] - v;
    if (t == 1023) d_blocksums[blockIdx.x] = s[t];
}

__global__ void scan2_kernel() {
    __shared__ int s[128];
    int t = threadIdx.x;
    int v = d_blocksums[t];
    s[t] = v; __syncthreads();
    for (int off = 1; off < 128; off <<= 1) {
        int tmp = (t >= off) ? s[t - off] : 0;
        __syncthreads();
        s[t] += tmp;
        __syncthreads();
    }
    d_blocksums[t] = s[t] - v;  // exclusive
}

__global__ void scan3_kernel() {
    int i = blockIdx.x * blockDim.x + threadIdx.x;
    if (i < NN) {
        int r = d_rowptr[i] + d_blocksums[i >> 10];
        d_rowptr[i] = r;
        d_cursor[i] = r;
        if (i == 0) d_rowptr[NN] = EE;
    }
}

__global__ void scatter_kernel(const int* __restrict__ src, const int* __restrict__ dst) {
    int e = blockIdx.x * blockDim.x + threadIdx.x;
    if (e < EE) {
        int p = atomicAdd(&d_cursor[dst[e]], 1);
        d_csr_src[p] = src[e];
    }
}

// ---------------- conv1: SAGE (2 -> 64), warp per node ----------------
__global__ void conv1_kernel(const float* __restrict__ x,
                             const float* __restrict__ Wl, const float* __restrict__ bl,
                             const float* __restrict__ Wr, const float* __restrict__ wp) {
    int gw = (blockIdx.x * blockDim.x + threadIdx.x) >> 5;
    if (gw >= NN) return;
    int lane = threadIdx.x & 31;
    const float2* x2 = (const float2*)x;
    int row = d_rowptr[gw], end = d_rowptr[gw + 1];
    float a0 = 0.f, a1 = 0.f;
    for (int e = row + lane; e < end; e += 32) {
        float2 v = x2[d_csr_src[e]];
        a0 += v.x;
        a1 += v.y;
    }
    for (int o = 16; o; o >>= 1) {
        a0 += __shfl_xor_sync(0xffffffffu, a0, o);
        a1 += __shfl_xor_sync(0xffffffffu, a1, o);
    }
    float deg = (float)(end - row);
    float inv = deg > 0.f ? 1.f / deg : 0.f;
    float m0 = a0 * inv, m1 = a1 * inv;
    float2 xv = x2[gw];
    int d0 = lane, d1 = lane + 32;
    float o0 = Wl[d0 * 2] * m0 + Wl[d0 * 2 + 1] * m1 + bl[d0] + Wr[d0 * 2] * xv.x + Wr[d0 * 2 + 1] * xv.y;
    float o1 = Wl[d1 * 2] * m0 + Wl[d1 * 2 + 1] * m1 + bl[d1] + Wr[d1 * 2] * xv.x + Wr[d1 * 2 + 1] * xv.y;
    o0 = fmaxf(o0, 0.f); o1 = fmaxf(o1, 0.f);
    d_hA[gw * 64 + d0] = o0;
    d_hA[gw * 64 + d1] = o1;
    float w0 = wp[d0], w1 = wp[d1];
    float sd = o0 * w0 + o1 * w1, nw = w0 * w0 + w1 * w1;
    for (int o = 16; o; o >>= 1) {
        sd += __shfl_xor_sync(0xffffffffu, sd, o);
        nw += __shfl_xor_sync(0xffffffffu, nw, o);
    }
    if (lane == 0) d_score[gw] = tanhf(sd * rsqrtf(nw));
}

// ---------------- fused radix select + compact (one block per graph) ----------------
__global__ void __launch_bounds__(1024, 1) selcompact_kernel(int m, int k, int flip) {
    __shared__ unsigned hist[256];
    __shared__ unsigned s_pref;
    __shared__ int s_rem;
    __shared__ int s_ctr;
    __shared__ int s_eq;
    int b = blockIdx.x, t = threadIdx.x;
    int lane = t & 31;
    int base = b * m;
    if (t == 0) { s_pref = 0u; s_rem = k; }
    __syncthreads();
    for (int p = 3; p >= 0; p--) {
        if (t < 256) hist[t] = 0;
        __syncthreads();
        unsigned pref = s_pref;
        int hs = (p + 1) * 8;
        for (int i = t; i < m; i += 1024) {
            unsigned u = fkey(d_score[base + i]);
            bool cand = (p == 3) || ((u >> hs) == (pref >> hs));
            if (cand) atomicAdd(&hist[(u >> (p * 8)) & 255], 1u);
        }
        __syncthreads();
        if (t == 0) {
            int rem = s_rem;
            unsigned c = 0;
            for (int bb = 255; bb >= 0; bb--) {
                if (c + hist[bb] >= (unsigned)rem) {
                    s_pref = pref | ((unsigned)bb << (p * 8));
                    s_rem = rem - (int)c;
                    break;
                }
                c += hist[bb];
            }
        }
        __syncthreads();
    }
    if (t == 0) { s_ctr = 0; s_eq = 0; }
    __syncthreads();
    unsigned th = s_pref;
    int quota = s_rem;
    const int* oldm = flip ? d_c2oB : d_c2oA;
    int* newm = flip ? d_c2oA : d_c2oB;
    // compact phase: m divisible by 1024 so the strided loop is warp-uniform
    for (int i = t; i < m; i += 1024) {
        int c = base + i;
        unsigned u = fkey(d_score[c]);
        bool keep = u > th;
        if (!keep && u == th) keep = (atomicAdd(&s_eq, 1) < quota);
        int orig = oldm[c];
        unsigned keepers = __ballot_sync(0xffffffffu, keep);
        int cnt = __popc(keepers);
        int base_slot = 0;
        if (lane == 0 && cnt > 0) base_slot = atomicAdd(&s_ctr, cnt);
        base_slot = __shfl_sync(0xffffffffu, base_slot, 0);
        if (keep) {
            int slot = base_slot + __popc(keepers & ((1u << lane) - 1u));
            int nc = b * k + slot;
            newm[nc] = orig;
            d_o2c[orig] = nc;
            d_oldidx[nc] = c;
        } else {
            d_o2c[orig] = -1;
        }
    }
}

// ---------------- pool copy + fused readout partials ----------------
__global__ void __launch_bounds__(256) copyro_kernel(int k, int stage) {
    __shared__ float sv[8][64];
    int gw = (blockIdx.x * blockDim.x + threadIdx.x) >> 5;
    int w = (threadIdx.x >> 5);
    int lane = threadIdx.x & 31;
    int oldc = d_oldidx[gw];
    float v = d_score[oldc];
    float2 h = *(const float2*)&d_hA[oldc * 64 + 2 * lane];
    float v0 = h.x * v, v1 = h.y * v;
    *(float2*)&d_hB[gw * 64 + 2 * lane] = make_float2(v0, v1);
    sv[w][2 * lane] = v0;
    sv[w][2 * lane + 1] = v1;
    __syncthreads();
    int t = threadIdx.x;
    if (t < 64) {
        float mx = sv[0][t], sm = 0.f;
        #pragma unroll
        for (int ww = 0; ww < 8; ww++) {
            float f = sv[ww][t];
            mx = fmaxf(mx, f);
            sm += f;
        }
        int b = (blockIdx.x * 8) / k;
        int off = stage * GB * 64 + b * 64 + t;
        atomicMax(&d_romax[off], fkey(mx));
        atomicAdd(&d_rosum[off], sm);
    }
}

// ---------------- SAGE2 fused: MLP-4 agg + tiled transform ----------------
__global__ void __launch_bounds__(256) sage_fused_kernel(const float* __restrict__ bl,
                                                         const float* __restrict__ wp) {
    __shared__ float sWl[4096];
    __shared__ float sWr[4096];
    __shared__ float sm_m[32][64];
    int t = threadIdx.x;
    for (int i = t; i < 4096; i += 256) {
        sWl[i] = d_WT[0][i];
        sWr[i] = d_WT[1][i];
    }
    int lane = t & 31;
    int w = t >> 5;
    int nblock = blockIdx.x * 32;

    // phase A: aggregation with 4 independent accumulator chains
    for (int q = 0; q < 4; q++) {
        int n = nblock + w * 4 + q;
        int o = d_c2oB[n];
        int row = d_rowptr[o], end = d_rowptr[o + 1];
        float a0x = 0.f, a0y = 0.f, a1x = 0.f, a1y = 0.f;
        float a2x = 0.f, a2y = 0.f, a3x = 0.f, a3y = 0.f;
        int cnt = 0;
        for (int base = row; base < end; base += 32) {
            int e = base + lane;
            int sc = (e < end) ? d_o2c[d_csr_src[e]] : -1;
            cnt += __popc(__ballot_sync(0xffffffffu, sc >= 0));
            #pragma unroll
            for (int j = 0; j < 32; j += 4) {
                int s0 = __shfl_sync(0xffffffffu, sc, j);
                int s1 = __shfl_sync(0xffffffffu, sc, j + 1);
                int s2 = __shfl_sync(0xffffffffu, sc, j + 2);
                int s3 = __shfl_sync(0xffffffffu, sc, j + 3);
                float2 v0 = (s0 >= 0) ? *(const float2*)&d_hB[s0 * 64 + 2 * lane] : make_float2(0.f, 0.f);
                float2 v1 = (s1 >= 0) ? *(const float2*)&d_hB[s1 * 64 + 2 * lane] : make_float2(0.f, 0.f);
                float2 v2 = (s2 >= 0) ? *(const float2*)&d_hB[s2 * 64 + 2 * lane] : make_float2(0.f, 0.f);
                float2 v3 = (s3 >= 0) ? *(const float2*)&d_hB[s3 * 64 + 2 * lane] : make_float2(0.f, 0.f);
                a0x += v0.x; a0y += v0.y;
                a1x += v1.x; a1y += v1.y;
                a2x += v2.x; a2y += v2.y;
                a3x += v3.x; a3y += v3.y;
            }
        }
        float invc = cnt ? 1.f / (float)cnt : 0.f;
        sm_m[w * 4 + q][2 * lane] = (a0x + a1x + a2x + a3x) * invc;
        sm_m[w * 4 + q][2 * lane + 1] = (a0y + a1y + a2y + a3y) * invc;
    }
    __syncthreads();

    // phase B: transform, warp w handles same 4 nodes, dims {lane, lane+32}
    int n0 = nblock + w * 4;
    float mA[4], mB[4], hA[4], hB[4], o0[4], o1[4];
    #pragma unroll
    for (int q = 0; q < 4; q++) {
        int n = n0 + q;
        mA[q] = sm_m[w * 4 + q][lane];
        mB[q] = sm_m[w * 4 + q][lane + 32];
        hA[q] = d_hB[n * 64 + lane];
        hB[q] = d_hB[n * 64 + lane + 32];
        o0[q] = 0.f; o1[q] = 0.f;
    }
    #pragma unroll 4
    for (int j = 0; j < 32; j++) {
        float wl0 = sWl[j * 64 + lane], wl1 = sWl[j * 64 + lane + 32];
        float wr0 = sWr[j * 64 + lane], wr1 = sWr[j * 64 + lane + 32];
        #pragma unroll
        for (int q = 0; q < 4; q++) {
            float mj = __shfl_sync(0xffffffffu, mA[q], j);
            float hj = __shfl_sync(0xffffffffu, hA[q], j);
            o0[q] += wl0 * mj + wr0 * hj;
            o1[q] += wl1 * mj + wr1 * hj;
        }
    }
    #pragma unroll 4
    for (int j = 32; j < 64; j++) {
        float wl0 = sWl[j * 64 + lane], wl1 = sWl[j * 64 + lane + 32];
        float wr0 = sWr[j * 64 + lane], wr1 = sWr[j * 64 + lane + 32];
        #pragma unroll
        for (int q = 0; q < 4; q++) {
            float mj = __shfl_sync(0xffffffffu, mB[q], j - 32);
            float hj = __shfl_sync(0xffffffffu, hB[q], j - 32);
            o0[q] += wl0 * mj + wr0 * hj;
            o1[q] += wl1 * mj + wr1 * hj;
        }
    }
    float b0 = bl[lane], b1 = bl[lane + 32];
    float w0 = wp[lane], w1 = wp[lane + 32];
    float nw = w0 * w0 + w1 * w1;
    for (int o = 16; o; o >>= 1) nw += __shfl_xor_sync(0xffffffffu, nw, o);
    float rn = rsqrtf(nw);
    #pragma unroll
    for (int q = 0; q < 4; q++) {
        int n = n0 + q;
        float r0 = fmaxf(o0[q] + b0, 0.f);
        float r1 = fmaxf(o1[q] + b1, 0.f);
        d_hA[n * 64 + lane] = r0;
        d_hA[n * 64 + lane + 32] = r1;
        float sd = r0 * w0 + r1 * w1;
        for (int o = 16; o; o >>= 1) sd += __shfl_xor_sync(0xffffffffu, sd, o);
        if (lane == 0) d_score[n] = tanhf(sd * rn);
    }
}

// ---------------- GCN xw transform (tiled) + fused degree ----------------
__global__ void __launch_bounds__(256) xwdeg_kernel(int M, int slot, int sel) {
    __shared__ float sW[4096];
    int t = threadIdx.x;
    for (int i = t; i < 4096; i += 256) sW[i] = d_WT[slot][i];
    __syncthreads();
    int lane = t & 31;
    int gw = (blockIdx.x * 8) + (t >> 5);
    int n0 = gw * 4;
    float hA[4], hB[4], o0[4], o1[4];
    #pragma unroll
    for (int q = 0; q < 4; q++) {
        int n = n0 + q;
        hA[q] = d_hB[n * 64 + lane];
        hB[q] = d_hB[n * 64 + lane + 32];
        o0[q] = 0.f; o1[q] = 0.f;
    }
    #pragma unroll 4
    for (int j = 0; j < 32; j++) {
        float w0 = sW[j * 64 + lane], w1 = sW[j * 64 + lane + 32];
        #pragma unroll
        for (int q = 0; q < 4; q++) {
            float hj = __shfl_sync(0xffffffffu, hA[q], j);
            o0[q] += w0 * hj;
            o1[q] += w1 * hj;
        }
    }
    #pragma unroll 4
    for (int j = 32; j < 64; j++) {
        float w0 = sW[j * 64 + lane], w1 = sW[j * 64 + lane + 32];
        #pragma unroll
        for (int q = 0; q < 4; q++) {
            float hj = __shfl_sync(0xffffffffu, hB[q], j - 32);
            o0[q] += w0 * hj;
            o1[q] += w1 * hj;
        }
    }
    const int* c2o = sel ? d_c2oB : d_c2oA;
    #pragma unroll
    for (int q = 0; q < 4; q++) {
        int n = n0 + q;
        d_xw[n * 64 + lane] = o0[q];
        d_xw[n * 64 + lane + 32] = o1[q];
        int o = c2o[n];
        int row = d_rowptr[o], end = d_rowptr[o + 1];
        int cnt = 0;
        for (int base = row; base < end; base += 32) {
            int e = base + lane;
            bool live = false;
            if (e < end) live = (d_o2c[d_csr_src[e]] >= 0);
            cnt += __popc(__ballot_sync(0xffffffffu, live));
        }
        if (lane == 0) d_dis[n] = rsqrtf(1.f + (float)cnt);
    }
}

// ---------------- GCN aggregation + epilogue (MLP-4) ----------------
__global__ void __launch_bounds__(256) gcn_kernel(int M, const float* __restrict__ bias,
                                                  const float* __restrict__ wp, int sel) {
    int gw = (blockIdx.x * blockDim.x + threadIdx.x) >> 5;
    if (gw >= M) return;
    int lane = threadIdx.x & 31;
    const int* c2o = sel ? d_c2oB : d_c2oA;
    int o = c2o[gw];
    float dd = d_dis[gw];
    int row = d_rowptr[o], end = d_rowptr[o + 1];
    float a0x = 0.f, a0y = 0.f, a1x = 0.f, a1y = 0.f;
    float a2x = 0.f, a2y = 0.f, a3x = 0.f, a3y = 0.f;
    for (int base = row; base < end; base += 32) {
        int e = base + lane;
        int sc = -1;
        float ds = 0.f;
        if (e < end) {
            sc = d_o2c[d_csr_src[e]];
            if (sc >= 0) ds = d_dis[sc];
        }
        #pragma unroll
        for (int j = 0; j < 32; j += 4) {
            int s0 = __shfl_sync(0xffffffffu, sc, j);
            int s1 = __shfl_sync(0xffffffffu, sc, j + 1);
            int s2 = __shfl_sync(0xffffffffu, sc, j + 2);
            int s3 = __shfl_sync(0xffffffffu, sc, j + 3);
            float d0 = __shfl_sync(0xffffffffu, ds, j);
            float d1 = __shfl_sync(0xffffffffu, ds, j + 1);
            float d2 = __shfl_sync(0xffffffffu, ds, j + 2);
            float d3 = __shfl_sync(0xffffffffu, ds, j + 3);
            float2 v0 = (s0 >= 0) ? *(const float2*)&d_xw[s0 * 64 + 2 * lane] : make_float2(0.f, 0.f);
            float2 v1 = (s1 >= 0) ? *(const float2*)&d_xw[s1 * 64 + 2 * lane] : make_float2(0.f, 0.f);
            float2 v2 = (s2 >= 0) ? *(const float2*)&d_xw[s2 * 64 + 2 * lane] : make_float2(0.f, 0.f);
            float2 v3 = (s3 >= 0) ? *(const float2*)&d_xw[s3 * 64 + 2 * lane] : make_float2(0.f, 0.f);
            a0x += v0.x * d0; a0y += v0.y * d0;
            a1x += v1.x * d1; a1y += v1.y * d1;
            a2x += v2.x * d2; a2y += v2.y * d2;
            a3x += v3.x * d3; a3y += v3.y * d3;
        }
    }
    float ax = (a0x + a1x + a2x + a3x) * dd;
    float ay = (a0y + a1y + a2y + a3y) * dd;
    float2 self = *(const float2*)&d_xw[gw * 64 + 2 * lane];
    float o0 = ax + self.x * dd * dd + bias[2 * lane];
    float o1 = ay + self.y * dd * dd + bias[2 * lane + 1];
    o0 = fmaxf(o0, 0.f); o1 = fmaxf(o1, 0.f);
    *(float2*)&d_hA[gw * 64 + 2 * lane] = make_float2(o0, o1);
    float w0 = wp[2 * lane], w1 = wp[2 * lane + 1];
    float sd = o0 * w0 + o1 * w1, nw = w0 * w0 + w1 * w1;
    for (int s = 16; s; s >>= 1) {
        sd += __shfl_xor_sync(0xffffffffu, sd, s);
        nw += __shfl_xor_sync(0xffffffffu, nw, s);
    }
    if (lane == 0) d_score[gw] = tanhf(sd * rsqrtf(nw));
}

// ---------------- final MLP + softmax ----------------
__global__ void __launch_bounds__(1024, 1) mlp_kernel(const float* __restrict__ Wa, const float* __restrict__ ba,
                           const float* __restrict__ Wb, const float* __restrict__ bb,
                           const float* __restrict__ Wc, const float* __restrict__ bc,
                           float* __restrict__ out) {
    __shared__ float zs[1024];
    __shared__ float za[1024];
    __shared__ float zb[512];
    __shared__ float zc[2048];
    int t = threadIdx.x;
    {
        int b = t >> 7, d = t & 127;
        const float invk[4] = {1.f / 8192.f, 1.f / 4096.f, 1.f / 2048.f, 1.f / 1024.f};
        float acc = 0.f;
        if (d < 64) {
            #pragma unroll
            for (int st = 0; st < 4; st++)
                acc += unfkey(d_romax[st * GB * 64 + b * 64 + d]);
        } else {
            #pragma unroll
            for (int st = 0; st < 4; st++)
                acc += d_rosum[st * GB * 64 + b * 64 + (d - 64)] * invk[st];
        }
        zs[t] = acc;
    }
    __syncthreads();
    {
        int b = t >> 7, o = t & 127;
        float a = ba[o];
        const float* w = Wa + o * 128;
        const float* z = zs + b * 128;
        for (int j = 0; j < 128; j++) a += w[j] * z[j];
        za[t] = fmaxf(a, 0.f);
    }
    __syncthreads();
    if (t < 512) {
        int b = t >> 6, o = t & 63;
        float a = bb[o];
        for (int j = 0; j < 128; j++) a += Wb[o * 128 + j] * za[b * 128 + j];
        zb[t] = fmaxf(a, 0.f);
    }
    __syncthreads();
    for (int q = t; q < 2048; q += 1024) {
        int b = q >> 8, o = q & 255;
        float a = bc[o];
        for (int j = 0; j < 64; j++) a += Wc[o * 64 + j] * zb[b * 64 + j];
        zc[q] = a;
    }
    __syncthreads();
    int w = t >> 5, lane = t & 31;
    if (w < 8) {
        float mx = -3.4e38f;
        for (int i = lane; i < 256; i += 32) mx = fmaxf(mx, zc[w * 256 + i]);
        for (int o = 16; o; o >>= 1) mx = fmaxf(mx, __shfl_xor_sync(0xffffffffu, mx, o));
        float s = 0.f;
        for (int i = lane; i < 256; i += 32) {
            float e = expf(zc[w * 256 + i] - mx);
            zc[w * 256 + i] = e;
            s += e;
        }
        for (int o = 16; o; o >>= 1) s += __shfl_xor_sync(0xffffffffu, s, o);
        float inv = 1.f / s;
        for (int i = lane; i < 256; i += 32) out[w * 256 + i] = zc[w * 256 + i] * inv;
    }
}

// ---------------- launch ----------------
extern "C" void kernel_launch(void* const* d_in, const int* in_sizes, int n_in,
                              void* d_out, int out_size) {
    const float* x = (const float*)d_in[0];
    const int* ei = (const int*)d_in[1];
    const int* src = ei;
    const int* dst = ei + EE;
    const float* Wl1 = (const float*)d_in[2];
    const float* bl1 = (const float*)d_in[3];
    const float* Wr1 = (const float*)d_in[4];
    const float* Wl2 = (const float*)d_in[5];
    const float* bl2 = (const float*)d_in[6];
    const float* Wr2 = (const float*)d_in[7];
    const float* W4  = (const float*)d_in[8];
    const float* b4  = (const float*)d_in[9];
    const float* W5  = (const float*)d_in[10];
    const float* b5  = (const float*)d_in[11];
    const float* wp1 = (const float*)d_in[12];
    const float* wp2 = (const float*)d_in[13];
    const float* wp4 = (const float*)d_in[14];
    const float* wp5 = (const float*)d_in[15];
    const float* Wa  = (const float*)d_in[16];
    const float* ba  = (const float*)d_in[17];
    const float* Wb  = (const float*)d_in[18];
    const float* bb  = (const float*)d_in[19];
    const float* Wc  = (const float*)d_in[20];
    const float* bc  = (const float*)d_in[21];
    float* out = (float*)d_out;

    // CSR build (+ weight transpose folded into init)
    init_kernel<<<NN / 256, 256>>>(Wl2, Wr2, W4, W5);
    hist_kernel<<<EE / 256, 256>>>(dst);
    scan1_kernel<<<128, 1024>>>();
    scan2_kernel<<<1, 128>>>();
    scan3_kernel<<<NN / 256, 256>>>();
    scatter_kernel<<<EE / 256, 256>>>(src, dst);

    // stage 1: SAGE1 on all N nodes, pool 16384 -> 8192
    conv1_kernel<<<NN / 8, 256>>>(x, Wl1, bl1, Wr1, wp1);
    selcompact_kernel<<<GB, 1024>>>(16384, 8192, 0);
    copyro_kernel<<<(GB * 8192) / 8, 256>>>(8192, 0);

    // stage 2: SAGE2 on 65536 nodes (fused agg+transform), pool 8192 -> 4096
    sage_fused_kernel<<<65536 / 32, 256>>>(bl2, wp2);
    selcompact_kernel<<<GB, 1024>>>(8192, 4096, 1);
    copyro_kernel<<<(GB * 4096) / 8, 256>>>(4096, 1);

    // stage 3: GCN on 32768 nodes, pool 4096 -> 2048
    xwdeg_kernel<<<32768 / 32, 256>>>(32768, 2, 0);
    gcn_kernel<<<32768 / 8, 256>>>(32768, b4, wp4, 0);
    selcompact_kernel<<<GB, 1024>>>(4096, 2048, 0);
    copyro_kernel<<<(GB * 2048) / 8, 256>>>(2048, 2);

    // stage 4: GCN on 16384 nodes, pool 2048 -> 1024
    xwdeg_kernel<<<16384 / 32, 256>>>(16384, 3, 1);
    gcn_kernel<<<16384 / 8, 256>>>(16384, b5, wp5, 1);
    selcompact_kernel<<<GB, 1024>>>(2048, 1024, 1);
    copyro_kernel<<<(GB * 1024) / 8, 256>>>(1024, 3);

    // final MLP + softmax
    mlp_kernel<<<1, 1024>>>(Wa, ba, Wb, bb, Wc, bc, out);
}

// round 13
// speedup vs baseline: 1.9281x; 1.1414x over previous
#include <cuda_runtime.h>

#define NN 131072
#define EE 2097152
#define GB 8
#define CWD 64

// ---------------- static device scratch ----------------
__device__ __align__(16) int d_cnt[NN];
__device__ int d_rowptr[NN + 1];
__device__ int d_cursor[NN];
__device__ int d_csr_src[EE];
__device__ unsigned d_agg[128];          // lookback aggregates (flag in bit31)
__device__ float d_hA[NN * CWD];
__device__ float d_hB[NN * CWD];
__device__ float d_xw[NN * CWD];
__device__ float d_score[NN];
__device__ float d_dis[NN];
__device__ int d_c2oA[NN];
__device__ int d_c2oB[NN];
__device__ int d_o2c[NN];
__device__ int d_oldidx[NN];
__device__ unsigned d_romax[4 * GB * CWD];
__device__ float d_rosum[4 * GB * CWD];
__device__ float d_WT[4][CWD * CWD];  // transposed Wl2, Wr2, W4, W5

__device__ __forceinline__ unsigned fkey(float f) {
    unsigned b = __float_as_uint(f);
    return (b & 0x80000000u) ? ~b : (b | 0x80000000u);
}
__device__ __forceinline__ float unfkey(unsigned u) {
    unsigned b = (u & 0x80000000u) ? (u & 0x7fffffffu) : ~u;
    return __uint_as_float(b);
}

__device__ __forceinline__ int wscan_incl(int v, int lane) {
    int incl = v;
    #pragma unroll
    for (int off = 1; off < 32; off <<= 1) {
        int n = __shfl_up_sync(0xffffffffu, incl, off);
        if (lane >= off) incl += n;
    }
    return incl;
}

// ---------------- hist + folded init work ----------------
__global__ void hist_kernel(const int* __restrict__ dst,
                            const float* __restrict__ Wl2, const float* __restrict__ Wr2,
                            const float* __restrict__ W4, const float* __restrict__ W5) {
    int e = blockIdx.x * blockDim.x + threadIdx.x;
    atomicAdd(&d_cnt[dst[e]], 1);
    if (e < 4 * GB * CWD) { d_romax[e] = 0u; d_rosum[e] = 0.f; }
    if (e < 4 * 4096) {
        int slot = e >> 12;
        int j = e & 4095;
        const float* W = slot == 0 ? Wl2 : slot == 1 ? Wr2 : slot == 2 ? W4 : W5;
        int r = j >> 6, c = j & 63;
        d_WT[slot][c * 64 + r] = W[j];
    }
}

// ---------------- single-kernel scan (decoupled lookback, 128 blocks co-resident) ----------------
__global__ void __launch_bounds__(256, 4) scanfused_kernel() {
    __shared__ int s_warp[8];
    __shared__ int s_off;
    int t = threadIdx.x, b = blockIdx.x;
    int lane = t & 31, w = t >> 5;
    int i0 = b * 1024 + t * 4;
    int4 v = *(const int4*)&d_cnt[i0];
    int s = v.x + v.y + v.z + v.w;
    int incl = wscan_incl(s, lane);
    if (lane == 31) s_warp[w] = incl;
    __syncthreads();
    if (t == 0) {
        int acc = 0;
        #pragma unroll
        for (int ww = 0; ww < 8; ww++) { int tmp = s_warp[ww]; s_warp[ww] = acc; acc += tmp; }
        __threadfence();
        ((volatile unsigned*)d_agg)[b] = (unsigned)acc | 0x80000000u;   // publish aggregate
    } else if (w == 1) {
        // lookback: sum published aggregates of all predecessor blocks
        int off = 0;
        for (int j = lane; j < b; j += 32) {
            unsigned a;
            do { a = ((volatile unsigned*)d_agg)[j]; } while (!(a >> 31));
            off += (int)(a & 0x7fffffffu);
        }
        for (int o = 16; o; o >>= 1) off += __shfl_xor_sync(0xffffffffu, off, o);
        if (lane == 0) s_off = off;
    }
    __syncthreads();
    int ex = s_off + s_warp[w] + incl - s;
    d_rowptr[i0] = ex;
    d_rowptr[i0 + 1] = ex + v.x;
    d_rowptr[i0 + 2] = ex + v.x + v.y;
    d_rowptr[i0 + 3] = ex + v.x + v.y + v.z;
    d_cursor[i0] = ex;
    d_cursor[i0 + 1] = ex + v.x;
    d_cursor[i0 + 2] = ex + v.x + v.y;
    d_cursor[i0 + 3] = ex + v.x + v.y + v.z;
    *(int4*)&d_cnt[i0] = make_int4(0, 0, 0, 0);   // re-zero for next call
    if (b == 127 && t == 0) d_rowptr[NN] = EE;
}

__global__ void scatter_kernel(const int* __restrict__ src, const int* __restrict__ dst) {
    int e = blockIdx.x * blockDim.x + threadIdx.x;
    int p = atomicAdd(&d_cursor[dst[e]], 1);
    d_csr_src[p] = src[e];
    if (e < 128) d_agg[e] = 0;   // reset lookback flags for next call
}

// ---------------- conv1: SAGE (2 -> 64), warp per node ----------------
__global__ void conv1_kernel(const float* __restrict__ x,
                             const float* __restrict__ Wl, const float* __restrict__ bl,
                             const float* __restrict__ Wr, const float* __restrict__ wp) {
    int gw = (blockIdx.x * blockDim.x + threadIdx.x) >> 5;
    if (gw >= NN) return;
    int lane = threadIdx.x & 31;
    const float2* x2 = (const float2*)x;
    int row = d_rowptr[gw], end = d_rowptr[gw + 1];
    float a0 = 0.f, a1 = 0.f;
    for (int e = row + lane; e < end; e += 32) {
        float2 v = x2[d_csr_src[e]];
        a0 += v.x;
        a1 += v.y;
    }
    for (int o = 16; o; o >>= 1) {
        a0 += __shfl_xor_sync(0xffffffffu, a0, o);
        a1 += __shfl_xor_sync(0xffffffffu, a1, o);
    }
    float deg = (float)(end - row);
    float inv = deg > 0.f ? 1.f / deg : 0.f;
    float m0 = a0 * inv, m1 = a1 * inv;
    float2 xv = x2[gw];
    int d0 = lane, d1 = lane + 32;
    float o0 = Wl[d0 * 2] * m0 + Wl[d0 * 2 + 1] * m1 + bl[d0] + Wr[d0 * 2] * xv.x + Wr[d0 * 2 + 1] * xv.y;
    float o1 = Wl[d1 * 2] * m0 + Wl[d1 * 2 + 1] * m1 + bl[d1] + Wr[d1 * 2] * xv.x + Wr[d1 * 2 + 1] * xv.y;
    o0 = fmaxf(o0, 0.f); o1 = fmaxf(o1, 0.f);
    d_hA[gw * 64 + d0] = o0;
    d_hA[gw * 64 + d1] = o1;
    float w0 = wp[d0], w1 = wp[d1];
    float sd = o0 * w0 + o1 * w1, nw = w0 * w0 + w1 * w1;
    for (int o = 16; o; o >>= 1) {
        sd += __shfl_xor_sync(0xffffffffu, sd, o);
        nw += __shfl_xor_sync(0xffffffffu, nw, o);
    }
    if (lane == 0) d_score[gw] = tanhf(sd * rsqrtf(nw));
}

// ---------------- fused radix select + compact (one block per graph, parallel bin scan) ----------------
__global__ void __launch_bounds__(1024, 1) selcompact_kernel(int m, int k, int flip, int identity) {
    __shared__ unsigned hist[256];
    __shared__ int s_wsum[8];
    __shared__ unsigned s_pref;
    __shared__ int s_rem;
    __shared__ int s_ctr;
    __shared__ int s_eq;
    int b = blockIdx.x, t = threadIdx.x;
    int lane = t & 31;
    int base = b * m;
    if (t == 0) { s_pref = 0u; s_rem = k; }
    __syncthreads();
    for (int p = 3; p >= 0; p--) {
        if (t < 256) hist[t] = 0;
        __syncthreads();
        unsigned pref = s_pref;
        int rem_in = s_rem;
        int hs = (p + 1) * 8;
        for (int i = t; i < m; i += 1024) {
            unsigned u = fkey(d_score[base + i]);
            bool cand = (p == 3) || ((u >> hs) == (pref >> hs));
            if (cand) atomicAdd(&hist[(u >> (p * 8)) & 255], 1u);
        }
        __syncthreads();
        // parallel suffix scan over 256 bins (descending) + unique-writer select
        unsigned x = 0, incl = 0;
        if (t < 256) {
            int rt = 255 - t;
            x = hist[rt];
            incl = (unsigned)wscan_incl((int)x, lane);
            if (lane == 31) s_wsum[t >> 5] = (int)incl;
        }
        __syncthreads();
        if (t == 0) {
            int acc = 0;
            #pragma unroll
            for (int ww = 0; ww < 8; ww++) { int tmp = s_wsum[ww]; s_wsum[ww] = acc; acc += tmp; }
        }
        __syncthreads();
        if (t < 256) {
            int rt = 255 - t;
            unsigned g = (unsigned)s_wsum[t >> 5] + incl;   // inclusive suffix sum at bin rt
            unsigned above = g - x;
            if ((unsigned)rem_in > above && (unsigned)rem_in <= g) {
                s_pref = pref | ((unsigned)rt << (p * 8));
                s_rem = rem_in - (int)above;
            }
        }
        __syncthreads();
    }
    if (t == 0) { s_ctr = 0; s_eq = 0; }
    __syncthreads();
    unsigned th = s_pref;
    int quota = s_rem;
    const int* oldm = flip ? d_c2oB : d_c2oA;
    int* newm = flip ? d_c2oA : d_c2oB;
    for (int i = t; i < m; i += 1024) {
        int c = base + i;
        unsigned u = fkey(d_score[c]);
        bool keep = u > th;
        if (!keep && u == th) keep = (atomicAdd(&s_eq, 1) < quota);
        int orig = identity ? c : oldm[c];
        unsigned keepers = __ballot_sync(0xffffffffu, keep);
        int cnt = __popc(keepers);
        int base_slot = 0;
        if (lane == 0 && cnt > 0) base_slot = atomicAdd(&s_ctr, cnt);
        base_slot = __shfl_sync(0xffffffffu, base_slot, 0);
        if (keep) {
            int slot = base_slot + __popc(keepers & ((1u << lane) - 1u));
            int nc = b * k + slot;
            newm[nc] = orig;
            d_o2c[orig] = nc;
            d_oldidx[nc] = c;
        } else {
            d_o2c[orig] = -1;
        }
    }
}

// ---------------- pool copy + fused readout partials ----------------
__global__ void __launch_bounds__(256) copyro_kernel(int k, int stage) {
    __shared__ float sv[8][64];
    int gw = (blockIdx.x * blockDim.x + threadIdx.x) >> 5;
    int w = (threadIdx.x >> 5);
    int lane = threadIdx.x & 31;
    int oldc = d_oldidx[gw];
    float v = d_score[oldc];
    float2 h = *(const float2*)&d_hA[oldc * 64 + 2 * lane];
    float v0 = h.x * v, v1 = h.y * v;
    *(float2*)&d_hB[gw * 64 + 2 * lane] = make_float2(v0, v1);
    sv[w][2 * lane] = v0;
    sv[w][2 * lane + 1] = v1;
    __syncthreads();
    int t = threadIdx.x;
    if (t < 64) {
        float mx = sv[0][t], sm = 0.f;
        #pragma unroll
        for (int ww = 0; ww < 8; ww++) {
            float f = sv[ww][t];
            mx = fmaxf(mx, f);
            sm += f;
        }
        int b = (blockIdx.x * 8) / k;
        int off = stage * GB * 64 + b * 64 + t;
        atomicMax(&d_romax[off], fkey(mx));
        atomicAdd(&d_rosum[off], sm);
    }
}

// ---------------- SAGE2 fused: MLP-4 agg + tiled transform ----------------
__global__ void __launch_bounds__(256) sage_fused_kernel(const float* __restrict__ bl,
                                                         const float* __restrict__ wp) {
    __shared__ float sWl[4096];
    __shared__ float sWr[4096];
    __shared__ float sm_m[32][64];
    int t = threadIdx.x;
    for (int i = t; i < 4096; i += 256) {
        sWl[i] = d_WT[0][i];
        sWr[i] = d_WT[1][i];
    }
    int lane = t & 31;
    int w = t >> 5;
    int nblock = blockIdx.x * 32;

    for (int q = 0; q < 4; q++) {
        int n = nblock + w * 4 + q;
        int o = d_c2oB[n];
        int row = d_rowptr[o], end = d_rowptr[o + 1];
        float a0x = 0.f, a0y = 0.f, a1x = 0.f, a1y = 0.f;
        float a2x = 0.f, a2y = 0.f, a3x = 0.f, a3y = 0.f;
        int cnt = 0;
        for (int base = row; base < end; base += 32) {
            int e = base + lane;
            int sc = (e < end) ? d_o2c[d_csr_src[e]] : -1;
            cnt += __popc(__ballot_sync(0xffffffffu, sc >= 0));
            #pragma unroll
            for (int j = 0; j < 32; j += 4) {
                int s0 = __shfl_sync(0xffffffffu, sc, j);
                int s1 = __shfl_sync(0xffffffffu, sc, j + 1);
                int s2 = __shfl_sync(0xffffffffu, sc, j + 2);
                int s3 = __shfl_sync(0xffffffffu, sc, j + 3);
                float2 v0 = (s0 >= 0) ? *(const float2*)&d_hB[s0 * 64 + 2 * lane] : make_float2(0.f, 0.f);
                float2 v1 = (s1 >= 0) ? *(const float2*)&d_hB[s1 * 64 + 2 * lane] : make_float2(0.f, 0.f);
                float2 v2 = (s2 >= 0) ? *(const float2*)&d_hB[s2 * 64 + 2 * lane] : make_float2(0.f, 0.f);
                float2 v3 = (s3 >= 0) ? *(const float2*)&d_hB[s3 * 64 + 2 * lane] : make_float2(0.f, 0.f);
                a0x += v0.x; a0y += v0.y;
                a1x += v1.x; a1y += v1.y;
                a2x += v2.x; a2y += v2.y;
                a3x += v3.x; a3y += v3.y;
            }
        }
        float invc = cnt ? 1.f / (float)cnt : 0.f;
        sm_m[w * 4 + q][2 * lane] = (a0x + a1x + a2x + a3x) * invc;
        sm_m[w * 4 + q][2 * lane + 1] = (a0y + a1y + a2y + a3y) * invc;
    }
    __syncthreads();

    int n0 = nblock + w * 4;
    float mA[4], mB[4], hA[4], hB[4], o0[4], o1[4];
    #pragma unroll
    for (int q = 0; q < 4; q++) {
        int n = n0 + q;
        mA[q] = sm_m[w * 4 + q][lane];
        mB[q] = sm_m[w * 4 + q][lane + 32];
        hA[q] = d_hB[n * 64 + lane];
        hB[q] = d_hB[n * 64 + lane + 32];
        o0[q] = 0.f; o1[q] = 0.f;
    }
    #pragma unroll 4
    for (int j = 0; j < 32; j++) {
        float wl0 = sWl[j * 64 + lane], wl1 = sWl[j * 64 + lane + 32];
        float wr0 = sWr[j * 64 + lane], wr1 = sWr[j * 64 + lane + 32];
        #pragma unroll
        for (int q = 0; q < 4; q++) {
            float mj = __shfl_sync(0xffffffffu, mA[q], j);
            float hj = __shfl_sync(0xffffffffu, hA[q], j);
            o0[q] += wl0 * mj + wr0 * hj;
            o1[q] += wl1 * mj + wr1 * hj;
        }
    }
    #pragma unroll 4
    for (int j = 32; j < 64; j++) {
        float wl0 = sWl[j * 64 + lane], wl1 = sWl[j * 64 + lane + 32];
        float wr0 = sWr[j * 64 + lane], wr1 = sWr[j * 64 + lane + 32];
        #pragma unroll
        for (int q = 0; q < 4; q++) {
            float mj = __shfl_sync(0xffffffffu, mB[q], j - 32);
            float hj = __shfl_sync(0xffffffffu, hB[q], j - 32);
            o0[q] += wl0 * mj + wr0 * hj;
            o1[q] += wl1 * mj + wr1 * hj;
        }
    }
    float b0 = bl[lane], b1 = bl[lane + 32];
    float w0 = wp[lane], w1 = wp[lane + 32];
    float nw = w0 * w0 + w1 * w1;
    for (int o = 16; o; o >>= 1) nw += __shfl_xor_sync(0xffffffffu, nw, o);
    float rn = rsqrtf(nw);
    #pragma unroll
    for (int q = 0; q < 4; q++) {
        int n = n0 + q;
        float r0 = fmaxf(o0[q] + b0, 0.f);
        float r1 = fmaxf(o1[q] + b1, 0.f);
        d_hA[n * 64 + lane] = r0;
        d_hA[n * 64 + lane + 32] = r1;
        float sd = r0 * w0 + r1 * w1;
        for (int o = 16; o; o >>= 1) sd += __shfl_xor_sync(0xffffffffu, sd, o);
        if (lane == 0) d_score[n] = tanhf(sd * rn);
    }
}

// ---------------- GCN xw transform (tiled) + fused degree ----------------
__global__ void __launch_bounds__(256) xwdeg_kernel(int M, int slot, int sel) {
    __shared__ float sW[4096];
    int t = threadIdx.x;
    for (int i = t; i < 4096; i += 256) sW[i] = d_WT[slot][i];
    __syncthreads();
    int lane = t & 31;
    int gw = (blockIdx.x * 8) + (t >> 5);
    int n0 = gw * 4;
    float hA[4], hB[4], o0[4], o1[4];
    #pragma unroll
    for (int q = 0; q < 4; q++) {
        int n = n0 + q;
        hA[q] = d_hB[n * 64 + lane];
        hB[q] = d_hB[n * 64 + lane + 32];
        o0[q] = 0.f; o1[q] = 0.f;
    }
    #pragma unroll 4
    for (int j = 0; j < 32; j++) {
        float w0 = sW[j * 64 + lane], w1 = sW[j * 64 + lane + 32];
        #pragma unroll
        for (int q = 0; q < 4; q++) {
            float hj = __shfl_sync(0xffffffffu, hA[q], j);
            o0[q] += w0 * hj;
            o1[q] += w1 * hj;
        }
    }
    #pragma unroll 4
    for (int j = 32; j < 64; j++) {
        float w0 = sW[j * 64 + lane], w1 = sW[j * 64 + lane + 32];
        #pragma unroll
        for (int q = 0; q < 4; q++) {
            float hj = __shfl_sync(0xffffffffu, hB[q], j - 32);
            o0[q] += w0 * hj;
            o1[q] += w1 * hj;
        }
    }
    const int* c2o = sel ? d_c2oB : d_c2oA;
    #pragma unroll
    for (int q = 0; q < 4; q++) {
        int n = n0 + q;
        d_xw[n * 64 + lane] = o0[q];
        d_xw[n * 64 + lane + 32] = o1[q];
        int o = c2o[n];
        int row = d_rowptr[o], end = d_rowptr[o + 1];
        int cnt = 0;
        for (int base = row; base < end; base += 32) {
            int e = base + lane;
            bool live = false;
            if (e < end) live = (d_o2c[d_csr_src[e]] >= 0);
            cnt += __popc(__ballot_sync(0xffffffffu, live));
        }
        if (lane == 0) d_dis[n] = rsqrtf(1.f + (float)cnt);
    }
}

// ---------------- GCN aggregation + epilogue (MLP-4) ----------------
__global__ void __launch_bounds__(256) gcn_kernel(int M, const float* __restrict__ bias,
                                                  const float* __restrict__ wp, int sel) {
    int gw = (blockIdx.x * blockDim.x + threadIdx.x) >> 5;
    if (gw >= M) return;
    int lane = threadIdx.x & 31;
    const int* c2o = sel ? d_c2oB : d_c2oA;
    int o = c2o[gw];
    float dd = d_dis[gw];
    int row = d_rowptr[o], end = d_rowptr[o + 1];
    float a0x = 0.f, a0y = 0.f, a1x = 0.f, a1y = 0.f;
    float a2x = 0.f, a2y = 0.f, a3x = 0.f, a3y = 0.f;
    for (int base = row; base < end; base += 32) {
        int e = base + lane;
        int sc = -1;
        float ds = 0.f;
        if (e < end) {
            sc = d_o2c[d_csr_src[e]];
            if (sc >= 0) ds = d_dis[sc];
        }
        #pragma unroll
        for (int j = 0; j < 32; j += 4) {
            int s0 = __shfl_sync(0xffffffffu, sc, j);
            int s1 = __shfl_sync(0xffffffffu, sc, j + 1);
            int s2 = __shfl_sync(0xffffffffu, sc, j + 2);
            int s3 = __shfl_sync(0xffffffffu, sc, j + 3);
            float d0 = __shfl_sync(0xffffffffu, ds, j);
            float d1 = __shfl_sync(0xffffffffu, ds, j + 1);
            float d2 = __shfl_sync(0xffffffffu, ds, j + 2);
            float d3 = __shfl_sync(0xffffffffu, ds, j + 3);
            float2 v0 = (s0 >= 0) ? *(const float2*)&d_xw[s0 * 64 + 2 * lane] : make_float2(0.f, 0.f);
            float2 v1 = (s1 >= 0) ? *(const float2*)&d_xw[s1 * 64 + 2 * lane] : make_float2(0.f, 0.f);
            float2 v2 = (s2 >= 0) ? *(const float2*)&d_xw[s2 * 64 + 2 * lane] : make_float2(0.f, 0.f);
            float2 v3 = (s3 >= 0) ? *(const float2*)&d_xw[s3 * 64 + 2 * lane] : make_float2(0.f, 0.f);
            a0x += v0.x * d0; a0y += v0.y * d0;
            a1x += v1.x * d1; a1y += v1.y * d1;
            a2x += v2.x * d2; a2y += v2.y * d2;
            a3x += v3.x * d3; a3y += v3.y * d3;
        }
    }
    float ax = (a0x + a1x + a2x + a3x) * dd;
    float ay = (a0y + a1y + a2y + a3y) * dd;
    float2 self = *(const float2*)&d_xw[gw * 64 + 2 * lane];
    float o0 = ax + self.x * dd * dd + bias[2 * lane];
    float o1 = ay + self.y * dd * dd + bias[2 * lane + 1];
    o0 = fmaxf(o0, 0.f); o1 = fmaxf(o1, 0.f);
    *(float2*)&d_hA[gw * 64 + 2 * lane] = make_float2(o0, o1);
    float w0 = wp[2 * lane], w1 = wp[2 * lane + 1];
    float sd = o0 * w0 + o1 * w1, nw = w0 * w0 + w1 * w1;
    for (int s = 16; s; s >>= 1) {
        sd += __shfl_xor_sync(0xffffffffu, sd, s);
        nw += __shfl_xor_sync(0xffffffffu, nw, s);
    }
    if (lane == 0) d_score[gw] = tanhf(sd * rsqrtf(nw));
}

// ---------------- final MLP + softmax ----------------
__global__ void __launch_bounds__(1024, 1) mlp_kernel(const float* __restrict__ Wa, const float* __restrict__ ba,
                           const float* __restrict__ Wb, const float* __restrict__ bb,
                           const float* __restrict__ Wc, const float* __restrict__ bc,
                           float* __restrict__ out) {
    __shared__ float zs[1024];
    __shared__ float za[1024];
    __shared__ float zb[512];
    __shared__ float zc[2048];
    int t = threadIdx.x;
    {
        int b = t >> 7, d = t & 127;
        const float invk[4] = {1.f / 8192.f, 1.f / 4096.f, 1.f / 2048.f, 1.f / 1024.f};
        float acc = 0.f;
        if (d < 64) {
            #pragma unroll
            for (int st = 0; st < 4; st++)
                acc += unfkey(d_romax[st * GB * 64 + b * 64 + d]);
        } else {
            #pragma unroll
            for (int st = 0; st < 4; st++)
                acc += d_rosum[st * GB * 64 + b * 64 + (d - 64)] * invk[st];
        }
        zs[t] = acc;
    }
    __syncthreads();
    {
        int b = t >> 7, o = t & 127;
        float a = ba[o];
        const float* w = Wa + o * 128;
        const float* z = zs + b * 128;
        for (int j = 0; j < 128; j++) a += w[j] * z[j];
        za[t] = fmaxf(a, 0.f);
    }
    __syncthreads();
    if (t < 512) {
        int b = t >> 6, o = t & 63;
        float a = bb[o];
        for (int j = 0; j < 128; j++) a += Wb[o * 128 + j] * za[b * 128 + j];
        zb[t] = fmaxf(a, 0.f);
    }
    __syncthreads();
    for (int q = t; q < 2048; q += 1024) {
        int b = q >> 8, o = q & 255;
        float a = bc[o];
        for (int j = 0; j < 64; j++) a += Wc[o * 64 + j] * zb[b * 64 + j];
        zc[q] = a;
    }
    __syncthreads();
    int w = t >> 5, lane = t & 31;
    if (w < 8) {
        float mx = -3.4e38f;
        for (int i = lane; i < 256; i += 32) mx = fmaxf(mx, zc[w * 256 + i]);
        for (int o = 16; o; o >>= 1) mx = fmaxf(mx, __shfl_xor_sync(0xffffffffu, mx, o));
        float s = 0.f;
        for (int i = lane; i < 256; i += 32) {
            float e = expf(zc[w * 256 + i] - mx);
            zc[w * 256 + i] = e;
            s += e;
        }
        for (int o = 16; o; o >>= 1) s += __shfl_xor_sync(0xffffffffu, s, o);
        float inv = 1.f / s;
        for (int i = lane; i < 256; i += 32) out[w * 256 + i] = zc[w * 256 + i] * inv;
    }
}

// ---------------- launch ----------------
extern "C" void kernel_launch(void* const* d_in, const int* in_sizes, int n_in,
                              void* d_out, int out_size) {
    const float* x = (const float*)d_in[0];
    const int* ei = (const int*)d_in[1];
    const int* src = ei;
    const int* dst = ei + EE;
    const float* Wl1 = (const float*)d_in[2];
    const float* bl1 = (const float*)d_in[3];
    const float* Wr1 = (const float*)d_in[4];
    const float* Wl2 = (const float*)d_in[5];
    const float* bl2 = (const float*)d_in[6];
    const float* Wr2 = (const float*)d_in[7];
    const float* W4  = (const float*)d_in[8];
    const float* b4  = (const float*)d_in[9];
    const float* W5  = (const float*)d_in[10];
    const float* b5  = (const float*)d_in[11];
    const float* wp1 = (const float*)d_in[12];
    const float* wp2 = (const float*)d_in[13];
    const float* wp4 = (const float*)d_in[14];
    const float* wp5 = (const float*)d_in[15];
    const float* Wa  = (const float*)d_in[16];
    const float* ba  = (const float*)d_in[17];
    const float* Wb  = (const float*)d_in[18];
    const float* bb  = (const float*)d_in[19];
    const float* Wc  = (const float*)d_in[20];
    const float* bc  = (const float*)d_in[21];
    float* out = (float*)d_out;

    // CSR build (3 kernels; init folded away)
    hist_kernel<<<EE / 256, 256>>>(dst, Wl2, Wr2, W4, W5);
    scanfused_kernel<<<128, 256>>>();
    scatter_kernel<<<EE / 256, 256>>>(src, dst);

    // stage 1: SAGE1 on all N nodes, pool 16384 -> 8192
    conv1_kernel<<<NN / 8, 256>>>(x, Wl1, bl1, Wr1, wp1);
    selcompact_kernel<<<GB, 1024>>>(16384, 8192, 0, 1);
    copyro_kernel<<<(GB * 8192) / 8, 256>>>(8192, 0);

    // stage 2: SAGE2 on 65536 nodes (fused agg+transform), pool 8192 -> 4096
    sage_fused_kernel<<<65536 / 32, 256>>>(bl2, wp2);
    selcompact_kernel<<<GB, 1024>>>(8192, 4096, 1, 0);
    copyro_kernel<<<(GB * 4096) / 8, 256>>>(4096, 1);

    // stage 3: GCN on 32768 nodes, pool 4096 -> 2048
    xwdeg_kernel<<<32768 / 32, 256>>>(32768, 2, 0);
    gcn_kernel<<<32768 / 8, 256>>>(32768, b4, wp4, 0);
    selcompact_kernel<<<GB, 1024>>>(4096, 2048, 0, 0);
    copyro_kernel<<<(GB * 2048) / 8, 256>>>(2048, 2);

    // stage 4: GCN on 16384 nodes, pool 2048 -> 1024
    xwdeg_kernel<<<16384 / 32, 256>>>(16384, 3, 1);
    gcn_kernel<<<16384 / 8, 256>>>(16384, b5, wp5, 1);
    selcompact_kernel<<<GB, 1024>>>(2048, 1024, 1, 0);
    copyro_kernel<<<(GB * 1024) / 8, 256>>>(1024, 3);

    // final MLP + softmax
    mlp_kernel<<<1, 1024>>>(Wa, ba, Wb, bb, Wc, bc, out);
}